// round 8
// baseline (speedup 1.0000x reference)
#include <cuda_runtime.h>
#include <cuda_fp16.h>
#include <cstdint>

#define N_USERS 100000
#define N_ITEMS 50000
#define N_NODES (N_USERS + N_ITEMS)
#define EMB 64
#define BATCH 4096
#define MAXDEG 128
#define QROWS (N_NODES + 1)            // last row = permanent zero (dummy pad target)

// ---- static scratch (no allocations; zero-initialized at module load) ----
__device__ __half g_q0[(size_t)QROWS * EMB];        // dinv*emb     (row N_NODES stays 0)
__device__ __half g_q1[(size_t)QROWS * EMB];
__device__ __half g_q2[(size_t)QROWS * EMB];
__device__ int    g_deg   [N_NODES];                // PADDED degree (multiple of 4)
__device__ float  g_dinv  [N_NODES];
__device__ int    g_cursor[N_NODES];                // zero-init; reset by k_dq each replay
__device__ int    g_col   [(size_t)N_NODES * MAXDEG]; // padded CSR

// ---------------------------------------------------------------------------
// Padded-CSR fill: 4 interactions per thread -> 8 independent atomic chains.
__global__ void k_fill(const int* __restrict__ eu, const int* __restrict__ ei,
                       int* __restrict__ cursor, int* __restrict__ col, int E) {
    int i0 = (blockIdx.x * blockDim.x + threadIdx.x) * 4;
    #pragma unroll
    for (int k = 0; k < 4; ++k) {
        int i = i0 + k;
        if (i < E) {
            int u  = __ldg(eu + i);
            int it = __ldg(ei + i) + N_USERS;
            int s1 = atomicAdd(&cursor[u],  1);
            int s2 = atomicAdd(&cursor[it], 1);
            if (s1 < MAXDEG) col[(size_t)u  * MAXDEG + s1] = it;
            if (s2 < MAXDEG) col[(size_t)it * MAXDEG + s2] = u;
        }
    }
}

// ---------------------------------------------------------------------------
// Warp-per-node: real deg -> dinv; padded deg (round up to 4) -> g_deg;
// pad slots point at the dummy zero row; cursor reset; q0 = dinv*emb (fp16).
__global__ void k_dq(int* __restrict__ cursor, int* __restrict__ deg,
                     float* __restrict__ dinv, int* __restrict__ col,
                     const float4* __restrict__ emb, uint2* __restrict__ q0) {
    int tid = blockIdx.x * blockDim.x + threadIdx.x;
    int n = tid >> 5;
    if (n >= N_NODES) return;
    int lane = tid & 31;

    float d; int real, dgp;
    if (lane == 0) {
        int c = cursor[n];
        cursor[n] = 0;                       // ready for next graph replay
        real = (c < MAXDEG) ? c : MAXDEG;
        dgp = (real + 3) & ~3;
        deg[n] = dgp;
        d = (real > 0) ? rsqrtf((float)real) : 1.0f;
        dinv[n] = d;
    }
    d    = __shfl_sync(0xFFFFFFFFu, d, 0);
    real = __shfl_sync(0xFFFFFFFFu, real, 0);
    dgp  = __shfl_sync(0xFFFFFFFFu, dgp, 0);

    // pad (<=3 slots) with dummy node index
    if (lane < dgp - real)
        col[(size_t)n * MAXDEG + real + lane] = N_NODES;

    if (lane < 16) {
        float4 x = emb[(size_t)n * (EMB / 4) + lane];
        __half2 a = __floats2half2_rn(x.x * d, x.y * d);
        __half2 b = __floats2half2_rn(x.z * d, x.w * d);
        uint2 o;
        o.x = *(unsigned*)&a;
        o.y = *(unsigned*)&b;
        q0[(size_t)n * (EMB / 4) + lane] = o;
    }
}

// ---------------------------------------------------------------------------
// Warp-cooperative fp16 row gather-sum, predicate-free inner body.
// Quarter-warp owns 4 consecutive (padded) slots per 16-edge iteration.
// Edges combined pairwise in fp16 (HADD2) before f32 accumulation.
// On return every lane holds the full-row sum for its 8 columns.
__device__ __forceinline__ void row_sum_h(const __half* __restrict__ qin,
                                          const int* __restrict__ colrow,
                                          int dgp, int lane, float acc[8]) {
    int quarter = lane >> 3;
    int sub = lane & 7;
    #pragma unroll
    for (int k = 0; k < 8; ++k) acc[k] = 0.0f;

    const uint4* q4 = (const uint4*)qin;

    for (int e0 = 0; e0 < dgp; e0 += 16) {
        int base = e0 + 4 * quarter;
        if (base < dgp) {
            int4 c4 = *(const int4*)(colrow + base);   // slots all valid (padded)
            uint4 va = q4[(unsigned)c4.x * (EMB / 8) + sub];
            uint4 vb = q4[(unsigned)c4.y * (EMB / 8) + sub];
            uint4 vc = q4[(unsigned)c4.z * (EMB / 8) + sub];
            uint4 vd = q4[(unsigned)c4.w * (EMB / 8) + sub];
            const __half2* ha = (const __half2*)&va;
            const __half2* hb = (const __half2*)&vb;
            const __half2* hc = (const __half2*)&vc;
            const __half2* hd = (const __half2*)&vd;
            #pragma unroll
            for (int k = 0; k < 4; ++k) {
                __half2 s0 = __hadd2(ha[k], hb[k]);    // pairwise fp16 combine
                __half2 s1 = __hadd2(hc[k], hd[k]);
                float2 f0 = __half22float2(s0);
                float2 f1 = __half22float2(s1);
                acc[2*k]   += f0.x + f1.x;
                acc[2*k+1] += f0.y + f1.y;
            }
        }
    }
    #pragma unroll
    for (int k = 0; k < 8; ++k) {
        acc[k] += __shfl_xor_sync(0xFFFFFFFFu, acc[k], 8);
        acc[k] += __shfl_xor_sync(0xFFFFFFFFu, acc[k], 16);
    }
}

// Pull layer: qout[n] = dinv[n]^2 * sum_{s in N(n)} qin[s]
__global__ void __launch_bounds__(256)
k_pull_h(const __half* __restrict__ qin, __half* __restrict__ qout,
         const int* __restrict__ deg, const int* __restrict__ col,
         const float* __restrict__ dinv) {
    int tid = blockIdx.x * blockDim.x + threadIdx.x;
    int n = tid >> 5;
    if (n >= N_NODES) return;
    int lane = tid & 31;

    float acc[8];
    row_sum_h(qin, col + (size_t)n * MAXDEG, deg[n], lane, acc);

    if (lane < 8) {
        float d = dinv[n];
        float s = d * d;
        __half2 h0 = __floats2half2_rn(acc[0] * s, acc[1] * s);
        __half2 h1 = __floats2half2_rn(acc[2] * s, acc[3] * s);
        __half2 h2 = __floats2half2_rn(acc[4] * s, acc[5] * s);
        __half2 h3 = __floats2half2_rn(acc[6] * s, acc[7] * s);
        uint4 o;
        o.x = *(unsigned*)&h0; o.y = *(unsigned*)&h1;
        o.z = *(unsigned*)&h2; o.w = *(unsigned*)&h3;
        *((uint4*)(qout + (size_t)n * EMB) + lane) = o;
    }
}

// ---------------------------------------------------------------------------
// Fused layer-3 + epilogue. One warp per (role, batch-row), n = node id:
//   rep3 = dinv[n] * sum q2[s]
//   final = 0.25 * ( emb[n] + sq*(q1[n]+q2[n]) + rep3 ),  sq = 1/dinv[n]
__global__ void __launch_bounds__(256)
k_final(float* __restrict__ out,
        const float* __restrict__ emb,
        const __half* __restrict__ q1,
        const __half* __restrict__ q2,
        const int* __restrict__ deg, const int* __restrict__ col,
        const float* __restrict__ dinv,
        const int* __restrict__ users, const int* __restrict__ pos,
        const int* __restrict__ neg) {
    int tid = blockIdx.x * blockDim.x + threadIdx.x;
    int w = tid >> 5;
    if (w >= 3 * BATCH) return;
    int lane = tid & 31;

    int role = w / BATCH;
    int b = w - role * BATCH;
    int n = (role == 0) ? users[b]
          : (role == 1) ? (N_USERS + pos[b])
                        : (N_USERS + neg[b]);

    float acc[8];
    row_sum_h(q2, col + (size_t)n * MAXDEG, deg[n], lane, acc);

    if (lane < 8) {
        float d = dinv[n];
        float sq = __fdividef(1.0f, d);   // sqrt(deg), or 1 when deg==0
        size_t ro = (size_t)n * EMB + lane * 8;

        float4 e0 = *(const float4*)(emb + ro);
        float4 e1 = *(const float4*)(emb + ro + 4);
        uint4 a1 = *((const uint4*)(q1 + (size_t)n * EMB) + lane);
        uint4 a2 = *((const uint4*)(q2 + (size_t)n * EMB) + lane);
        const __half2* h1 = (const __half2*)&a1;
        const __half2* h2 = (const __half2*)&a2;

        float r[8];
        #pragma unroll
        for (int k = 0; k < 4; ++k) {
            float2 f1 = __half22float2(h1[k]);
            float2 f2 = __half22float2(h2[k]);
            r[2*k]   = sq * (f1.x + f2.x) + d * acc[2*k];
            r[2*k+1] = sq * (f1.y + f2.y) + d * acc[2*k+1];
        }
        float4 o0, o1;
        o0.x = (e0.x + r[0]) * 0.25f; o0.y = (e0.y + r[1]) * 0.25f;
        o0.z = (e0.z + r[2]) * 0.25f; o0.w = (e0.w + r[3]) * 0.25f;
        o1.x = (e1.x + r[4]) * 0.25f; o1.y = (e1.y + r[5]) * 0.25f;
        o1.z = (e1.z + r[6]) * 0.25f; o1.w = (e1.w + r[7]) * 0.25f;

        size_t wo = (size_t)(role * BATCH + b) * EMB + lane * 8;
        *(float4*)(out + wo)     = o0;
        *(float4*)(out + wo + 4) = o1;
    }

    if (role == 0) {
        int p = N_USERS + pos[b];
        int g = N_USERS + neg[b];
        int c = lane * 2;
        float2 eu = *(const float2*)(emb + (size_t)n * EMB + c);
        float2 ep = *(const float2*)(emb + (size_t)p * EMB + c);
        float2 eg = *(const float2*)(emb + (size_t)g * EMB + c);
        float sum = eu.x * eu.x + eu.y * eu.y
                  + ep.x * ep.x + ep.y * ep.y
                  + eg.x * eg.x + eg.y * eg.y;
        #pragma unroll
        for (int off = 16; off > 0; off >>= 1)
            sum += __shfl_xor_sync(0xFFFFFFFFu, sum, off);
        if (lane == 0)
            out[(size_t)3 * BATCH * EMB + b] = sum;
    }
}

// ---------------------------------------------------------------------------
extern "C" void kernel_launch(void* const* d_in, const int* in_sizes, int n_in,
                              void* d_out, int out_size) {
    const float* emb   = (const float*)d_in[0];
    const int*   eu    = (const int*)  d_in[1];
    const int*   ei    = (const int*)  d_in[2];
    const int*   users = (const int*)  d_in[3];
    const int*   pos   = (const int*)  d_in[4];
    const int*   neg   = (const int*)  d_in[5];
    float* out = (float*)d_out;
    const int E = in_sizes[1];

    __half *q0, *q1, *q2;
    float *dinv;
    int *deg, *cursor, *col;
    cudaGetSymbolAddress((void**)&q0,     g_q0);
    cudaGetSymbolAddress((void**)&q1,     g_q1);
    cudaGetSymbolAddress((void**)&q2,     g_q2);
    cudaGetSymbolAddress((void**)&dinv,   g_dinv);
    cudaGetSymbolAddress((void**)&deg,    g_deg);
    cudaGetSymbolAddress((void**)&cursor, g_cursor);
    cudaGetSymbolAddress((void**)&col,    g_col);

    const int TB = 256;

    // ---- padded-CSR build ----
    k_fill<<<(E / 4 + TB - 1) / TB, TB>>>(eu, ei, cursor, col, E);
    k_dq<<<(N_NODES * 32 + TB - 1) / TB, TB>>>(cursor, deg, dinv, col,
                                               (const float4*)emb, (uint2*)q0);

    // ---- layers 1 & 2 ----
    const int pullBlocks = (N_NODES * 32 + TB - 1) / TB;
    k_pull_h<<<pullBlocks, TB>>>(q0, q1, deg, col, dinv);
    k_pull_h<<<pullBlocks, TB>>>(q1, q2, deg, col, dinv);

    // ---- fused layer 3 + epilogue ----
    const int finalBlocks = (3 * BATCH * 32 + TB - 1) / TB;
    k_final<<<finalBlocks, TB>>>(out, emb, q1, q2, deg, col, dinv,
                                 users, pos, neg);
}

// round 9
// speedup vs baseline: 1.1839x; 1.1839x over previous
#include <cuda_runtime.h>
#include <cuda_fp16.h>
#include <cstdint>

#define N_USERS 100000
#define N_ITEMS 50000
#define N_NODES (N_USERS + N_ITEMS)
#define EMB 64
#define BATCH 4096
#define E_MAX 1500000
#define QROWS (N_NODES + 1)            // last row = permanent zero (dummy pad target)

// ---- static scratch (no allocations; zero-initialized at module load) ----
__device__ __half g_q0[(size_t)QROWS * EMB];     // dinv*emb  (row N_NODES stays 0)
__device__ __half g_q1[(size_t)QROWS * EMB];
__device__ __half g_q2[(size_t)QROWS * EMB];
__device__ float  g_dinv  [N_NODES];
__device__ int    g_deg   [N_NODES];             // real degree (histogram)
__device__ int    g_rs    [N_NODES + 1];         // padded-degree exclusive scan
__device__ int    g_cursor[N_NODES];
__device__ int    g_col   [2 * E_MAX + 4 * N_NODES + 16];  // ~13.8 MB compact+pad
__device__ int    g_bsum  [256];

#define SCAN_T 1024
#define SCAN_BLOCKS ((N_NODES + SCAN_T - 1) / SCAN_T)   // 147

// ---------------------------------------------------------------------------
// degree histogram, 4 interactions per thread (8 independent atomic chains)
__global__ void k_hist(const int* __restrict__ eu, const int* __restrict__ ei,
                       int* __restrict__ deg, int E) {
    int i0 = (blockIdx.x * blockDim.x + threadIdx.x) * 4;
    #pragma unroll
    for (int k = 0; k < 4; ++k) {
        int i = i0 + k;
        if (i < E) {
            atomicAdd(&deg[__ldg(eu + i)], 1);
            atomicAdd(&deg[__ldg(ei + i) + N_USERS], 1);
        }
    }
}

// Block-local exclusive scan of PADDED degree -> rs (pre-offset), bsum,
// dinv = rsqrt(real deg), q0 = dinv*emb (fp16). Also zeroes deg for next replay.
__global__ void k_scan1(int* __restrict__ deg, int* __restrict__ rs,
                        int* __restrict__ bsum, float* __restrict__ dinv,
                        const float4* __restrict__ emb, uint2* __restrict__ q0) {
    __shared__ int sh[SCAN_T];
    int gid = blockIdx.x * SCAN_T + threadIdx.x;
    int real = 0;
    if (gid < N_NODES) {
        real = deg[gid];
        deg[gid] = 0;                               // ready for next graph replay
    }
    int v = (real + 3) & ~3;                        // padded degree
    float d = (real > 0) ? rsqrtf((float)real) : 1.0f;
    if (gid < N_NODES) dinv[gid] = d;
    sh[threadIdx.x] = v;
    __syncthreads();
    for (int off = 1; off < SCAN_T; off <<= 1) {
        int t = (threadIdx.x >= off) ? sh[threadIdx.x - off] : 0;
        __syncthreads();
        sh[threadIdx.x] += t;
        __syncthreads();
    }
    if (gid < N_NODES) rs[gid] = sh[threadIdx.x] - v;   // exclusive (pre-offset)
    if (threadIdx.x == SCAN_T - 1) bsum[blockIdx.x] = sh[threadIdx.x];

    if (gid < N_NODES) {
        const float4* e = emb + (size_t)gid * (EMB / 4);
        uint2* q = q0 + (size_t)gid * (EMB / 4);
        #pragma unroll
        for (int k = 0; k < EMB / 4; ++k) {
            float4 x = e[k];
            __half2 a = __floats2half2_rn(x.x * d, x.y * d);
            __half2 b = __floats2half2_rn(x.z * d, x.w * d);
            uint2 o;
            o.x = *(unsigned*)&a;
            o.y = *(unsigned*)&b;
            q[k] = o;
        }
    }
}

// Merged scan2+scan3: every block redundantly scans the 147 block sums,
// applies its offset, initializes cursor, writes sentinel.
__global__ void k_scanB(int* __restrict__ rs, const int* __restrict__ bsum,
                        int* __restrict__ cursor) {
    __shared__ int sh[256];
    int t = threadIdx.x;
    int v = 0;
    if (t < 256) {
        v = (t < SCAN_BLOCKS) ? bsum[t] : 0;
        sh[t] = v;
    }
    __syncthreads();
    for (int off = 1; off < 256; off <<= 1) {
        int tmp = (t < 256 && t >= off) ? sh[t - off] : 0;
        __syncthreads();
        if (t < 256) sh[t] += tmp;
        __syncthreads();
    }
    if (t < 256) sh[t] -= v;   // exclusive
    __syncthreads();

    int gid = blockIdx.x * SCAN_T + t;
    if (gid < N_NODES) {
        int r = rs[gid] + sh[blockIdx.x];
        rs[gid] = r;
        cursor[gid] = r;
    }
    if (blockIdx.x == 0 && t == 0)
        rs[N_NODES] = sh[SCAN_BLOCKS - 1] + bsum[SCAN_BLOCKS - 1];
}

// CSR fill, 4 interactions per thread (8 independent atomic chains)
__global__ void k_fill(const int* __restrict__ eu, const int* __restrict__ ei,
                       int* __restrict__ cursor, int* __restrict__ col, int E) {
    int i0 = (blockIdx.x * blockDim.x + threadIdx.x) * 4;
    #pragma unroll
    for (int k = 0; k < 4; ++k) {
        int i = i0 + k;
        if (i < E) {
            int u  = __ldg(eu + i);
            int it = __ldg(ei + i) + N_USERS;
            col[atomicAdd(&cursor[u],  1)] = it;
            col[atomicAdd(&cursor[it], 1)] = u;
        }
    }
}

// Fill the <=3 pad slots per row with the dummy (zero) node index.
__global__ void k_pad(const int* __restrict__ cursor, const int* __restrict__ rs,
                      int* __restrict__ col) {
    int n = blockIdx.x * blockDim.x + threadIdx.x;
    if (n >= N_NODES) return;
    int c = cursor[n];
    int end = rs[n + 1];
    while (c < end) col[c++] = N_NODES;
}

// ---------------------------------------------------------------------------
// Warp-cooperative fp16 row gather-sum over a 4-aligned padded row.
// Quarter-warp owns 4 consecutive slots per 16-edge iteration; lane loads
// uint4 (8 halfs) of its edge's row. No per-edge predicates.
// On return every lane holds the full-row sum for its 8 columns.
__device__ __forceinline__ void row_sum_h(const __half* __restrict__ qin,
                                          const int* __restrict__ col,
                                          int beg, int end, int lane,
                                          float acc[8]) {
    int quarter = lane >> 3;
    int sub = lane & 7;
    #pragma unroll
    for (int k = 0; k < 8; ++k) acc[k] = 0.0f;

    const uint4* q4 = (const uint4*)qin;

    for (int e0 = beg; e0 < end; e0 += 16) {
        int base = e0 + 4 * quarter;
        if (base < end) {                       // whole quartet valid (padded)
            int4 c4 = *(const int4*)(col + base);   // 16B-aligned (beg % 4 == 0)
            uint4 va = q4[(unsigned)c4.x * (EMB / 8) + sub];
            uint4 vb = q4[(unsigned)c4.y * (EMB / 8) + sub];
            uint4 vc = q4[(unsigned)c4.z * (EMB / 8) + sub];
            uint4 vd = q4[(unsigned)c4.w * (EMB / 8) + sub];
            const __half2* ha = (const __half2*)&va;
            const __half2* hb = (const __half2*)&vb;
            const __half2* hc = (const __half2*)&vc;
            const __half2* hd = (const __half2*)&vd;
            #pragma unroll
            for (int k = 0; k < 4; ++k) {
                float2 fa = __half22float2(ha[k]);
                float2 fb = __half22float2(hb[k]);
                float2 fc = __half22float2(hc[k]);
                float2 fd = __half22float2(hd[k]);
                acc[2*k]   += (fa.x + fb.x) + (fc.x + fd.x);
                acc[2*k+1] += (fa.y + fb.y) + (fc.y + fd.y);
            }
        }
    }
    #pragma unroll
    for (int k = 0; k < 8; ++k) {
        acc[k] += __shfl_xor_sync(0xFFFFFFFFu, acc[k], 8);
        acc[k] += __shfl_xor_sync(0xFFFFFFFFu, acc[k], 16);
    }
}

// Pull layer: qout[n] = dinv[n]^2 * sum_{s in N(n)} qin[s]
__global__ void __launch_bounds__(256)
k_pull_h(const __half* __restrict__ qin, __half* __restrict__ qout,
         const int* __restrict__ rs, const int* __restrict__ col,
         const float* __restrict__ dinv) {
    int tid = blockIdx.x * blockDim.x + threadIdx.x;
    int n = tid >> 5;
    if (n >= N_NODES) return;
    int lane = tid & 31;

    float acc[8];
    row_sum_h(qin, col, rs[n], rs[n + 1], lane, acc);

    if (lane < 8) {
        float d = dinv[n];
        float s = d * d;
        __half2 h0 = __floats2half2_rn(acc[0] * s, acc[1] * s);
        __half2 h1 = __floats2half2_rn(acc[2] * s, acc[3] * s);
        __half2 h2 = __floats2half2_rn(acc[4] * s, acc[5] * s);
        __half2 h3 = __floats2half2_rn(acc[6] * s, acc[7] * s);
        uint4 o;
        o.x = *(unsigned*)&h0; o.y = *(unsigned*)&h1;
        o.z = *(unsigned*)&h2; o.w = *(unsigned*)&h3;
        *((uint4*)(qout + (size_t)n * EMB) + lane) = o;
    }
}

// ---------------------------------------------------------------------------
// Fused layer-3 + epilogue. One warp per (role, batch-row), n = node id:
//   rep3 = dinv[n] * sum q2[s]
//   final = 0.25 * ( emb[n] + sq*(q1[n]+q2[n]) + rep3 ),  sq = 1/dinv[n]
__global__ void __launch_bounds__(256)
k_final(float* __restrict__ out,
        const float* __restrict__ emb,
        const __half* __restrict__ q1,
        const __half* __restrict__ q2,
        const int* __restrict__ rs, const int* __restrict__ col,
        const float* __restrict__ dinv,
        const int* __restrict__ users, const int* __restrict__ pos,
        const int* __restrict__ neg) {
    int tid = blockIdx.x * blockDim.x + threadIdx.x;
    int w = tid >> 5;
    if (w >= 3 * BATCH) return;
    int lane = tid & 31;

    int role = w / BATCH;
    int b = w - role * BATCH;
    int n = (role == 0) ? users[b]
          : (role == 1) ? (N_USERS + pos[b])
                        : (N_USERS + neg[b]);

    float acc[8];
    row_sum_h(q2, col, rs[n], rs[n + 1], lane, acc);

    if (lane < 8) {
        float d = dinv[n];
        float sq = __fdividef(1.0f, d);   // sqrt(deg), or 1 when deg==0
        size_t ro = (size_t)n * EMB + lane * 8;

        float4 e0 = *(const float4*)(emb + ro);
        float4 e1 = *(const float4*)(emb + ro + 4);
        uint4 a1 = *((const uint4*)(q1 + (size_t)n * EMB) + lane);
        uint4 a2 = *((const uint4*)(q2 + (size_t)n * EMB) + lane);
        const __half2* h1 = (const __half2*)&a1;
        const __half2* h2 = (const __half2*)&a2;

        float r[8];
        #pragma unroll
        for (int k = 0; k < 4; ++k) {
            float2 f1 = __half22float2(h1[k]);
            float2 f2 = __half22float2(h2[k]);
            r[2*k]   = sq * (f1.x + f2.x) + d * acc[2*k];
            r[2*k+1] = sq * (f1.y + f2.y) + d * acc[2*k+1];
        }
        float4 o0, o1;
        o0.x = (e0.x + r[0]) * 0.25f; o0.y = (e0.y + r[1]) * 0.25f;
        o0.z = (e0.z + r[2]) * 0.25f; o0.w = (e0.w + r[3]) * 0.25f;
        o1.x = (e1.x + r[4]) * 0.25f; o1.y = (e1.y + r[5]) * 0.25f;
        o1.z = (e1.z + r[6]) * 0.25f; o1.w = (e1.w + r[7]) * 0.25f;

        size_t wo = (size_t)(role * BATCH + b) * EMB + lane * 8;
        *(float4*)(out + wo)     = o0;
        *(float4*)(out + wo + 4) = o1;
    }

    if (role == 0) {
        int p = N_USERS + pos[b];
        int g = N_USERS + neg[b];
        int c = lane * 2;
        float2 eu = *(const float2*)(emb + (size_t)n * EMB + c);
        float2 ep = *(const float2*)(emb + (size_t)p * EMB + c);
        float2 eg = *(const float2*)(emb + (size_t)g * EMB + c);
        float sum = eu.x * eu.x + eu.y * eu.y
                  + ep.x * ep.x + ep.y * ep.y
                  + eg.x * eg.x + eg.y * eg.y;
        #pragma unroll
        for (int off = 16; off > 0; off >>= 1)
            sum += __shfl_xor_sync(0xFFFFFFFFu, sum, off);
        if (lane == 0)
            out[(size_t)3 * BATCH * EMB + b] = sum;
    }
}

// ---------------------------------------------------------------------------
extern "C" void kernel_launch(void* const* d_in, const int* in_sizes, int n_in,
                              void* d_out, int out_size) {
    const float* emb   = (const float*)d_in[0];
    const int*   eu    = (const int*)  d_in[1];
    const int*   ei    = (const int*)  d_in[2];
    const int*   users = (const int*)  d_in[3];
    const int*   pos   = (const int*)  d_in[4];
    const int*   neg   = (const int*)  d_in[5];
    float* out = (float*)d_out;
    const int E = in_sizes[1];

    __half *q0, *q1, *q2;
    float *dinv;
    int *deg, *rs, *cursor, *col, *bsum;
    cudaGetSymbolAddress((void**)&q0,     g_q0);
    cudaGetSymbolAddress((void**)&q1,     g_q1);
    cudaGetSymbolAddress((void**)&q2,     g_q2);
    cudaGetSymbolAddress((void**)&dinv,   g_dinv);
    cudaGetSymbolAddress((void**)&deg,    g_deg);
    cudaGetSymbolAddress((void**)&rs,     g_rs);
    cudaGetSymbolAddress((void**)&cursor, g_cursor);
    cudaGetSymbolAddress((void**)&col,    g_col);
    cudaGetSymbolAddress((void**)&bsum,   g_bsum);

    const int TB = 256;

    // ---- CSR build (deg zeroed at load / by previous replay's k_scan1) ----
    k_hist<<<(E / 4 + TB - 1) / TB, TB>>>(eu, ei, deg, E);
    k_scan1<<<SCAN_BLOCKS, SCAN_T>>>(deg, rs, bsum, dinv, (const float4*)emb,
                                     (uint2*)q0);
    k_scanB<<<SCAN_BLOCKS, SCAN_T>>>(rs, bsum, cursor);
    k_fill<<<(E / 4 + TB - 1) / TB, TB>>>(eu, ei, cursor, col, E);
    k_pad<<<(N_NODES + TB - 1) / TB, TB>>>(cursor, rs, col);

    // ---- layers 1 & 2 ----
    const int pullBlocks = (N_NODES * 32 + TB - 1) / TB;
    k_pull_h<<<pullBlocks, TB>>>(q0, q1, rs, col, dinv);
    k_pull_h<<<pullBlocks, TB>>>(q1, q2, rs, col, dinv);

    // ---- fused layer 3 + epilogue ----
    const int finalBlocks = (3 * BATCH * 32 + TB - 1) / TB;
    k_final<<<finalBlocks, TB>>>(out, emb, q1, q2, rs, col, dinv,
                                 users, pos, neg);
}

// round 10
// speedup vs baseline: 1.3299x; 1.1233x over previous
#include <cuda_runtime.h>
#include <cuda_fp16.h>
#include <cstdint>

#define N_USERS 100000
#define N_ITEMS 50000
#define N_NODES (N_USERS + N_ITEMS)
#define EMB 64
#define BATCH 4096
#define E_MAX 1500000
#define QROWS (N_NODES + 1)            // last row = permanent zero (dummy pad target)

// ---- static scratch (no allocations; zero-initialized at module load) ----
__device__ __half g_q0[(size_t)QROWS * EMB];     // dinv*emb  (row N_NODES stays 0)
__device__ __half g_q1[(size_t)QROWS * EMB];
__device__ __half g_q2[(size_t)QROWS * EMB];
__device__ float  g_dinv  [N_NODES];
__device__ int    g_deg   [N_NODES];             // real degree (histogram)
__device__ int    g_rs    [N_NODES + 1];         // padded-degree exclusive scan
__device__ int    g_cursor[N_NODES];
__device__ int    g_col   [2 * E_MAX + 4 * N_NODES + 16];  // ~13.8 MB compact+pad
__device__ int    g_bsum  [256];

#define SCAN_T 1024
#define SCAN_BLOCKS ((N_NODES + SCAN_T - 1) / SCAN_T)   // 147

// ---------------------------------------------------------------------------
// degree histogram (1 interaction/thread — ILP hurts: L2 atomic-RMW bound)
__global__ void k_hist(const int* __restrict__ eu, const int* __restrict__ ei,
                       int* __restrict__ deg, int E) {
    int i = blockIdx.x * blockDim.x + threadIdx.x;
    if (i >= E) return;
    atomicAdd(&deg[eu[i]], 1);
    atomicAdd(&deg[ei[i] + N_USERS], 1);
}

// Block-local exclusive scan of PADDED degree -> rs (pre-offset), bsum,
// dinv = rsqrt(real deg), q0 = dinv*emb (fp16). Also zeroes deg for next replay.
__global__ void k_scan1(int* __restrict__ deg, int* __restrict__ rs,
                        int* __restrict__ bsum, float* __restrict__ dinv,
                        const float4* __restrict__ emb, uint2* __restrict__ q0) {
    __shared__ int sh[SCAN_T];
    int gid = blockIdx.x * SCAN_T + threadIdx.x;
    int real = 0;
    if (gid < N_NODES) {
        real = deg[gid];
        deg[gid] = 0;                               // ready for next graph replay
    }
    int v = (real + 3) & ~3;                        // padded degree
    float d = (real > 0) ? rsqrtf((float)real) : 1.0f;
    if (gid < N_NODES) dinv[gid] = d;
    sh[threadIdx.x] = v;
    __syncthreads();
    for (int off = 1; off < SCAN_T; off <<= 1) {
        int t = (threadIdx.x >= off) ? sh[threadIdx.x - off] : 0;
        __syncthreads();
        sh[threadIdx.x] += t;
        __syncthreads();
    }
    if (gid < N_NODES) rs[gid] = sh[threadIdx.x] - v;   // exclusive (pre-offset)
    if (threadIdx.x == SCAN_T - 1) bsum[blockIdx.x] = sh[threadIdx.x];

    if (gid < N_NODES) {
        const float4* e = emb + (size_t)gid * (EMB / 4);
        uint2* q = q0 + (size_t)gid * (EMB / 4);
        #pragma unroll
        for (int k = 0; k < EMB / 4; ++k) {
            float4 x = e[k];
            __half2 a = __floats2half2_rn(x.x * d, x.y * d);
            __half2 b = __floats2half2_rn(x.z * d, x.w * d);
            uint2 o;
            o.x = *(unsigned*)&a;
            o.y = *(unsigned*)&b;
            q[k] = o;
        }
    }
}

// Merged scan2+scan3: every block redundantly scans the 147 block sums,
// applies its offset, initializes cursor, writes sentinel.
__global__ void k_scanB(int* __restrict__ rs, const int* __restrict__ bsum,
                        int* __restrict__ cursor) {
    __shared__ int sh[256];
    int t = threadIdx.x;
    int v = 0;
    if (t < 256) {
        v = (t < SCAN_BLOCKS) ? bsum[t] : 0;
        sh[t] = v;
    }
    __syncthreads();
    for (int off = 1; off < 256; off <<= 1) {
        int tmp = (t < 256 && t >= off) ? sh[t - off] : 0;
        __syncthreads();
        if (t < 256) sh[t] += tmp;
        __syncthreads();
    }
    if (t < 256) sh[t] -= v;   // exclusive
    __syncthreads();

    int gid = blockIdx.x * SCAN_T + t;
    if (gid < N_NODES) {
        int r = rs[gid] + sh[blockIdx.x];
        rs[gid] = r;
        cursor[gid] = r;
    }
    if (blockIdx.x == 0 && t == 0)
        rs[N_NODES] = sh[SCAN_BLOCKS - 1] + bsum[SCAN_BLOCKS - 1];
}

// CSR fill (1 interaction/thread)
__global__ void k_fill(const int* __restrict__ eu, const int* __restrict__ ei,
                       int* __restrict__ cursor, int* __restrict__ col, int E) {
    int i = blockIdx.x * blockDim.x + threadIdx.x;
    if (i >= E) return;
    int u  = eu[i];
    int it = ei[i] + N_USERS;
    col[atomicAdd(&cursor[u],  1)] = it;
    col[atomicAdd(&cursor[it], 1)] = u;
}

// Fill the <=3 pad slots per row with the dummy (zero) node index.
__global__ void k_pad(const int* __restrict__ cursor, const int* __restrict__ rs,
                      int* __restrict__ col) {
    int n = blockIdx.x * blockDim.x + threadIdx.x;
    if (n >= N_NODES) return;
    int c = cursor[n];
    int end = rs[n + 1];
    while (c < end) col[c++] = N_NODES;
}

// ---------------------------------------------------------------------------
// Warp-cooperative row gather-sum with fp16 TREE accumulation.
// Quarter-warp owns 4 consecutive slots per 16-edge iteration; lane loads
// uint4 (8 halfs). Per quartet: t0=a+b, t1=c+d, hacc += t0+t1 (all HADD2).
// One f32 conversion after the loop, then f32 shfl reduction.
// On return every lane holds the full-row f32 sum for its 8 columns.
__device__ __forceinline__ void row_sum_h(const __half* __restrict__ qin,
                                          const int* __restrict__ col,
                                          int beg, int end, int lane,
                                          float acc[8]) {
    int quarter = lane >> 3;
    int sub = lane & 7;

    __half2 hz = __floats2half2_rn(0.0f, 0.0f);
    __half2 hacc[4] = {hz, hz, hz, hz};

    const uint4* q4 = (const uint4*)qin;

    for (int e0 = beg; e0 < end; e0 += 16) {
        int base = e0 + 4 * quarter;
        if (base < end) {                       // whole quartet valid (padded)
            int4 c4 = *(const int4*)(col + base);   // 16B-aligned (beg % 4 == 0)
            uint4 va = q4[(unsigned)c4.x * (EMB / 8) + sub];
            uint4 vb = q4[(unsigned)c4.y * (EMB / 8) + sub];
            uint4 vc = q4[(unsigned)c4.z * (EMB / 8) + sub];
            uint4 vd = q4[(unsigned)c4.w * (EMB / 8) + sub];
            const __half2* ha = (const __half2*)&va;
            const __half2* hb = (const __half2*)&vb;
            const __half2* hc = (const __half2*)&vc;
            const __half2* hd = (const __half2*)&vd;
            #pragma unroll
            for (int k = 0; k < 4; ++k) {
                __half2 t0 = __hadd2(ha[k], hb[k]);
                __half2 t1 = __hadd2(hc[k], hd[k]);
                hacc[k] = __hadd2(hacc[k], __hadd2(t0, t1));
            }
        }
    }

    #pragma unroll
    for (int k = 0; k < 4; ++k) {
        float2 f = __half22float2(hacc[k]);
        acc[2*k]   = f.x;
        acc[2*k+1] = f.y;
    }
    #pragma unroll
    for (int k = 0; k < 8; ++k) {
        acc[k] += __shfl_xor_sync(0xFFFFFFFFu, acc[k], 8);
        acc[k] += __shfl_xor_sync(0xFFFFFFFFu, acc[k], 16);
    }
}

// Pull layer: qout[n] = dinv[n]^2 * sum_{s in N(n)} qin[s]
__global__ void __launch_bounds__(256)
k_pull_h(const __half* __restrict__ qin, __half* __restrict__ qout,
         const int* __restrict__ rs, const int* __restrict__ col,
         const float* __restrict__ dinv) {
    int tid = blockIdx.x * blockDim.x + threadIdx.x;
    int n = tid >> 5;
    if (n >= N_NODES) return;
    int lane = tid & 31;

    float acc[8];
    row_sum_h(qin, col, rs[n], rs[n + 1], lane, acc);

    if (lane < 8) {
        float d = dinv[n];
        float s = d * d;
        __half2 h0 = __floats2half2_rn(acc[0] * s, acc[1] * s);
        __half2 h1 = __floats2half2_rn(acc[2] * s, acc[3] * s);
        __half2 h2 = __floats2half2_rn(acc[4] * s, acc[5] * s);
        __half2 h3 = __floats2half2_rn(acc[6] * s, acc[7] * s);
        uint4 o;
        o.x = *(unsigned*)&h0; o.y = *(unsigned*)&h1;
        o.z = *(unsigned*)&h2; o.w = *(unsigned*)&h3;
        *((uint4*)(qout + (size_t)n * EMB) + lane) = o;
    }
}

// ---------------------------------------------------------------------------
// Fused layer-3 + epilogue. One warp per (role, batch-row), n = node id:
//   rep3 = dinv[n] * sum q2[s]
//   final = 0.25 * ( emb[n] + sq*(q1[n]+q2[n]) + rep3 ),  sq = 1/dinv[n]
__global__ void __launch_bounds__(256)
k_final(float* __restrict__ out,
        const float* __restrict__ emb,
        const __half* __restrict__ q1,
        const __half* __restrict__ q2,
        const int* __restrict__ rs, const int* __restrict__ col,
        const float* __restrict__ dinv,
        const int* __restrict__ users, const int* __restrict__ pos,
        const int* __restrict__ neg) {
    int tid = blockIdx.x * blockDim.x + threadIdx.x;
    int w = tid >> 5;
    if (w >= 3 * BATCH) return;
    int lane = tid & 31;

    int role = w / BATCH;
    int b = w - role * BATCH;
    int n = (role == 0) ? users[b]
          : (role == 1) ? (N_USERS + pos[b])
                        : (N_USERS + neg[b]);

    float acc[8];
    row_sum_h(q2, col, rs[n], rs[n + 1], lane, acc);

    if (lane < 8) {
        float d = dinv[n];
        float sq = __fdividef(1.0f, d);   // sqrt(deg), or 1 when deg==0
        size_t ro = (size_t)n * EMB + lane * 8;

        float4 e0 = *(const float4*)(emb + ro);
        float4 e1 = *(const float4*)(emb + ro + 4);
        uint4 a1 = *((const uint4*)(q1 + (size_t)n * EMB) + lane);
        uint4 a2 = *((const uint4*)(q2 + (size_t)n * EMB) + lane);
        const __half2* h1 = (const __half2*)&a1;
        const __half2* h2 = (const __half2*)&a2;

        float r[8];
        #pragma unroll
        for (int k = 0; k < 4; ++k) {
            float2 f1 = __half22float2(h1[k]);
            float2 f2 = __half22float2(h2[k]);
            r[2*k]   = sq * (f1.x + f2.x) + d * acc[2*k];
            r[2*k+1] = sq * (f1.y + f2.y) + d * acc[2*k+1];
        }
        float4 o0, o1;
        o0.x = (e0.x + r[0]) * 0.25f; o0.y = (e0.y + r[1]) * 0.25f;
        o0.z = (e0.z + r[2]) * 0.25f; o0.w = (e0.w + r[3]) * 0.25f;
        o1.x = (e1.x + r[4]) * 0.25f; o1.y = (e1.y + r[5]) * 0.25f;
        o1.z = (e1.z + r[6]) * 0.25f; o1.w = (e1.w + r[7]) * 0.25f;

        size_t wo = (size_t)(role * BATCH + b) * EMB + lane * 8;
        *(float4*)(out + wo)     = o0;
        *(float4*)(out + wo + 4) = o1;
    }

    if (role == 0) {
        int p = N_USERS + pos[b];
        int g = N_USERS + neg[b];
        int c = lane * 2;
        float2 eu = *(const float2*)(emb + (size_t)n * EMB + c);
        float2 ep = *(const float2*)(emb + (size_t)p * EMB + c);
        float2 eg = *(const float2*)(emb + (size_t)g * EMB + c);
        float sum = eu.x * eu.x + eu.y * eu.y
                  + ep.x * ep.x + ep.y * ep.y
                  + eg.x * eg.x + eg.y * eg.y;
        #pragma unroll
        for (int off = 16; off > 0; off >>= 1)
            sum += __shfl_xor_sync(0xFFFFFFFFu, sum, off);
        if (lane == 0)
            out[(size_t)3 * BATCH * EMB + b] = sum;
    }
}

// ---------------------------------------------------------------------------
extern "C" void kernel_launch(void* const* d_in, const int* in_sizes, int n_in,
                              void* d_out, int out_size) {
    const float* emb   = (const float*)d_in[0];
    const int*   eu    = (const int*)  d_in[1];
    const int*   ei    = (const int*)  d_in[2];
    const int*   users = (const int*)  d_in[3];
    const int*   pos   = (const int*)  d_in[4];
    const int*   neg   = (const int*)  d_in[5];
    float* out = (float*)d_out;
    const int E = in_sizes[1];

    __half *q0, *q1, *q2;
    float *dinv;
    int *deg, *rs, *cursor, *col, *bsum;
    cudaGetSymbolAddress((void**)&q0,     g_q0);
    cudaGetSymbolAddress((void**)&q1,     g_q1);
    cudaGetSymbolAddress((void**)&q2,     g_q2);
    cudaGetSymbolAddress((void**)&dinv,   g_dinv);
    cudaGetSymbolAddress((void**)&deg,    g_deg);
    cudaGetSymbolAddress((void**)&rs,     g_rs);
    cudaGetSymbolAddress((void**)&cursor, g_cursor);
    cudaGetSymbolAddress((void**)&col,    g_col);
    cudaGetSymbolAddress((void**)&bsum,   g_bsum);

    const int TB = 256;

    // ---- CSR build (deg zeroed at load / by previous replay's k_scan1) ----
    k_hist<<<(E + TB - 1) / TB, TB>>>(eu, ei, deg, E);
    k_scan1<<<SCAN_BLOCKS, SCAN_T>>>(deg, rs, bsum, dinv, (const float4*)emb,
                                     (uint2*)q0);
    k_scanB<<<SCAN_BLOCKS, SCAN_T>>>(rs, bsum, cursor);
    k_fill<<<(E + TB - 1) / TB, TB>>>(eu, ei, cursor, col, E);
    k_pad<<<(N_NODES + TB - 1) / TB, TB>>>(cursor, rs, col);

    // ---- layers 1 & 2 ----
    const int pullBlocks = (N_NODES * 32 + TB - 1) / TB;
    k_pull_h<<<pullBlocks, TB>>>(q0, q1, rs, col, dinv);
    k_pull_h<<<pullBlocks, TB>>>(q1, q2, rs, col, dinv);

    // ---- fused layer 3 + epilogue ----
    const int finalBlocks = (3 * BATCH * 32 + TB - 1) / TB;
    k_final<<<finalBlocks, TB>>>(out, emb, q1, q2, rs, col, dinv,
                                 users, pos, neg);
}

// round 11
// speedup vs baseline: 1.3859x; 1.0421x over previous
#include <cuda_runtime.h>
#include <cuda_fp16.h>
#include <cstdint>

#define N_USERS 100000
#define N_ITEMS 50000
#define N_NODES (N_USERS + N_ITEMS)
#define EMB 64
#define BATCH 4096
#define E_MAX 1500000
#define QROWS (N_NODES + 1)            // last row = permanent zero (dummy pad target)

// ---- static scratch (no allocations; zero-initialized at module load) ----
__device__ __half  g_q0[(size_t)QROWS * EMB];    // dinv*emb  (row N_NODES stays 0)
__device__ __half  g_q1[(size_t)QROWS * EMB];
__device__ __half  g_q2[(size_t)QROWS * EMB];
__device__ float   g_dinv [N_NODES];
__device__ int     g_deg  [N_NODES];             // real degree; zeroed by k_scanB each replay
__device__ int     g_rs   [N_NODES + 1];         // padded-degree exclusive scan
__device__ ushort2 g_slots[E_MAX];               // per-interaction row-local slots (6 MB)
__device__ int     g_col  [2 * E_MAX + 4 * N_NODES + 16];  // ~13.8 MB compact+pad
__device__ int     g_bsum [256];

#define SCAN_T 1024
#define SCAN_BLOCKS ((N_NODES + SCAN_T - 1) / SCAN_T)   // 147

// ---------------------------------------------------------------------------
// Degree histogram; the atomic return value IS the edge's row-local slot.
// One coalesced 4B slot store per interaction.
__global__ void k_hist(const int* __restrict__ eu, const int* __restrict__ ei,
                       int* __restrict__ deg, ushort2* __restrict__ slots, int E) {
    int i = blockIdx.x * blockDim.x + threadIdx.x;
    if (i >= E) return;
    int s1 = atomicAdd(&deg[eu[i]], 1);
    int s2 = atomicAdd(&deg[ei[i] + N_USERS], 1);
    slots[i] = make_ushort2((unsigned short)s1, (unsigned short)s2);
}

// Block-local exclusive scan of PADDED degree -> rs (pre-offset), bsum,
// dinv = rsqrt(real deg), q0 = dinv*emb (fp16). Does NOT zero deg (scanB does).
__global__ void k_scan1(const int* __restrict__ deg, int* __restrict__ rs,
                        int* __restrict__ bsum, float* __restrict__ dinv,
                        const float4* __restrict__ emb, uint2* __restrict__ q0) {
    __shared__ int sh[SCAN_T];
    int gid = blockIdx.x * SCAN_T + threadIdx.x;
    int real = (gid < N_NODES) ? deg[gid] : 0;
    int v = (real + 3) & ~3;                        // padded degree
    float d = (real > 0) ? rsqrtf((float)real) : 1.0f;
    if (gid < N_NODES) dinv[gid] = d;
    sh[threadIdx.x] = v;
    __syncthreads();
    for (int off = 1; off < SCAN_T; off <<= 1) {
        int t = (threadIdx.x >= off) ? sh[threadIdx.x - off] : 0;
        __syncthreads();
        sh[threadIdx.x] += t;
        __syncthreads();
    }
    if (gid < N_NODES) rs[gid] = sh[threadIdx.x] - v;   // exclusive (pre-offset)
    if (threadIdx.x == SCAN_T - 1) bsum[blockIdx.x] = sh[threadIdx.x];

    if (gid < N_NODES) {
        const float4* e = emb + (size_t)gid * (EMB / 4);
        uint2* q = q0 + (size_t)gid * (EMB / 4);
        #pragma unroll
        for (int k = 0; k < EMB / 4; ++k) {
            float4 x = e[k];
            __half2 a = __floats2half2_rn(x.x * d, x.y * d);
            __half2 b = __floats2half2_rn(x.z * d, x.w * d);
            uint2 o;
            o.x = *(unsigned*)&a;
            o.y = *(unsigned*)&b;
            q[k] = o;
        }
    }
}

// Merged scan2+scan3+pad: every block redundantly scans the 147 block sums,
// applies its offset to rs, PRE-writes the <=3 pad slots per row (disjoint from
// k_fill's slots, so order vs fill is irrelevant), zeroes deg for next replay,
// and writes the sentinel.
__global__ void k_scanB(int* __restrict__ rs, const int* __restrict__ bsum,
                        int* __restrict__ deg, int* __restrict__ col) {
    __shared__ int sh[256];
    int t = threadIdx.x;
    int v = 0;
    if (t < 256) {
        v = (t < SCAN_BLOCKS) ? bsum[t] : 0;
        sh[t] = v;
    }
    __syncthreads();
    for (int off = 1; off < 256; off <<= 1) {
        int tmp = (t < 256 && t >= off) ? sh[t - off] : 0;
        __syncthreads();
        if (t < 256) sh[t] += tmp;
        __syncthreads();
    }
    if (t < 256) sh[t] -= v;   // exclusive
    __syncthreads();

    int gid = blockIdx.x * SCAN_T + t;
    if (gid < N_NODES) {
        int r = rs[gid] + sh[blockIdx.x];
        rs[gid] = r;
        int real = deg[gid];
        deg[gid] = 0;                               // ready for next graph replay
        int pads = ((real + 3) & ~3) - real;        // 0..3
        int base = r + real;
        for (int k = 0; k < pads; ++k) col[base + k] = N_NODES;
    }
    if (blockIdx.x == 0 && t == 0)
        rs[N_NODES] = sh[SCAN_BLOCKS - 1] + bsum[SCAN_BLOCKS - 1];
}

// Atomic-free CSR fill: slot precomputed in k_hist, offset via rs gather.
__global__ void k_fill(const int* __restrict__ eu, const int* __restrict__ ei,
                       const ushort2* __restrict__ slots,
                       const int* __restrict__ rs, int* __restrict__ col, int E) {
    int i = blockIdx.x * blockDim.x + threadIdx.x;
    if (i >= E) return;
    int u  = eu[i];
    int it = ei[i] + N_USERS;
    ushort2 s = slots[i];
    col[__ldg(rs + u)  + s.x] = it;
    col[__ldg(rs + it) + s.y] = u;
}

// ---------------------------------------------------------------------------
// Warp-cooperative row gather-sum with fp16 TREE accumulation.
// Quarter-warp owns 4 consecutive slots per 16-edge iteration; lane loads
// uint4 (8 halfs). Per quartet: t0=a+b, t1=c+d, hacc += t0+t1 (all HADD2).
// One f32 conversion after the loop, then f32 shfl reduction.
__device__ __forceinline__ void row_sum_h(const __half* __restrict__ qin,
                                          const int* __restrict__ col,
                                          int beg, int end, int lane,
                                          float acc[8]) {
    int quarter = lane >> 3;
    int sub = lane & 7;

    __half2 hz = __floats2half2_rn(0.0f, 0.0f);
    __half2 hacc[4] = {hz, hz, hz, hz};

    const uint4* q4 = (const uint4*)qin;

    for (int e0 = beg; e0 < end; e0 += 16) {
        int base = e0 + 4 * quarter;
        if (base < end) {                       // whole quartet valid (padded)
            int4 c4 = *(const int4*)(col + base);   // 16B-aligned (beg % 4 == 0)
            uint4 va = q4[(unsigned)c4.x * (EMB / 8) + sub];
            uint4 vb = q4[(unsigned)c4.y * (EMB / 8) + sub];
            uint4 vc = q4[(unsigned)c4.z * (EMB / 8) + sub];
            uint4 vd = q4[(unsigned)c4.w * (EMB / 8) + sub];
            const __half2* ha = (const __half2*)&va;
            const __half2* hb = (const __half2*)&vb;
            const __half2* hc = (const __half2*)&vc;
            const __half2* hd = (const __half2*)&vd;
            #pragma unroll
            for (int k = 0; k < 4; ++k) {
                __half2 t0 = __hadd2(ha[k], hb[k]);
                __half2 t1 = __hadd2(hc[k], hd[k]);
                hacc[k] = __hadd2(hacc[k], __hadd2(t0, t1));
            }
        }
    }

    #pragma unroll
    for (int k = 0; k < 4; ++k) {
        float2 f = __half22float2(hacc[k]);
        acc[2*k]   = f.x;
        acc[2*k+1] = f.y;
    }
    #pragma unroll
    for (int k = 0; k < 8; ++k) {
        acc[k] += __shfl_xor_sync(0xFFFFFFFFu, acc[k], 8);
        acc[k] += __shfl_xor_sync(0xFFFFFFFFu, acc[k], 16);
    }
}

// Pull layer: qout[n] = dinv[n]^2 * sum_{s in N(n)} qin[s]
__global__ void __launch_bounds__(256)
k_pull_h(const __half* __restrict__ qin, __half* __restrict__ qout,
         const int* __restrict__ rs, const int* __restrict__ col,
         const float* __restrict__ dinv) {
    int tid = blockIdx.x * blockDim.x + threadIdx.x;
    int n = tid >> 5;
    if (n >= N_NODES) return;
    int lane = tid & 31;

    float acc[8];
    row_sum_h(qin, col, __ldg(rs + n), __ldg(rs + n + 1), lane, acc);

    if (lane < 8) {
        float d = dinv[n];
        float s = d * d;
        __half2 h0 = __floats2half2_rn(acc[0] * s, acc[1] * s);
        __half2 h1 = __floats2half2_rn(acc[2] * s, acc[3] * s);
        __half2 h2 = __floats2half2_rn(acc[4] * s, acc[5] * s);
        __half2 h3 = __floats2half2_rn(acc[6] * s, acc[7] * s);
        uint4 o;
        o.x = *(unsigned*)&h0; o.y = *(unsigned*)&h1;
        o.z = *(unsigned*)&h2; o.w = *(unsigned*)&h3;
        *((uint4*)(qout + (size_t)n * EMB) + lane) = o;
    }
}

// ---------------------------------------------------------------------------
// Fused layer-3 + epilogue. One warp per (role, batch-row), n = node id:
//   rep3 = dinv[n] * sum q2[s]
//   final = 0.25 * ( emb[n] + sq*(q1[n]+q2[n]) + rep3 ),  sq = 1/dinv[n]
__global__ void __launch_bounds__(256)
k_final(float* __restrict__ out,
        const float* __restrict__ emb,
        const __half* __restrict__ q1,
        const __half* __restrict__ q2,
        const int* __restrict__ rs, const int* __restrict__ col,
        const float* __restrict__ dinv,
        const int* __restrict__ users, const int* __restrict__ pos,
        const int* __restrict__ neg) {
    int tid = blockIdx.x * blockDim.x + threadIdx.x;
    int w = tid >> 5;
    if (w >= 3 * BATCH) return;
    int lane = tid & 31;

    int role = w / BATCH;
    int b = w - role * BATCH;
    int n = (role == 0) ? users[b]
          : (role == 1) ? (N_USERS + pos[b])
                        : (N_USERS + neg[b]);

    float acc[8];
    row_sum_h(q2, col, __ldg(rs + n), __ldg(rs + n + 1), lane, acc);

    if (lane < 8) {
        float d = dinv[n];
        float sq = __fdividef(1.0f, d);   // sqrt(deg), or 1 when deg==0
        size_t ro = (size_t)n * EMB + lane * 8;

        float4 e0 = *(const float4*)(emb + ro);
        float4 e1 = *(const float4*)(emb + ro + 4);
        uint4 a1 = *((const uint4*)(q1 + (size_t)n * EMB) + lane);
        uint4 a2 = *((const uint4*)(q2 + (size_t)n * EMB) + lane);
        const __half2* h1 = (const __half2*)&a1;
        const __half2* h2 = (const __half2*)&a2;

        float r[8];
        #pragma unroll
        for (int k = 0; k < 4; ++k) {
            float2 f1 = __half22float2(h1[k]);
            float2 f2 = __half22float2(h2[k]);
            r[2*k]   = sq * (f1.x + f2.x) + d * acc[2*k];
            r[2*k+1] = sq * (f1.y + f2.y) + d * acc[2*k+1];
        }
        float4 o0, o1;
        o0.x = (e0.x + r[0]) * 0.25f; o0.y = (e0.y + r[1]) * 0.25f;
        o0.z = (e0.z + r[2]) * 0.25f; o0.w = (e0.w + r[3]) * 0.25f;
        o1.x = (e1.x + r[4]) * 0.25f; o1.y = (e1.y + r[5]) * 0.25f;
        o1.z = (e1.z + r[6]) * 0.25f; o1.w = (e1.w + r[7]) * 0.25f;

        size_t wo = (size_t)(role * BATCH + b) * EMB + lane * 8;
        *(float4*)(out + wo)     = o0;
        *(float4*)(out + wo + 4) = o1;
    }

    if (role == 0) {
        int p = N_USERS + pos[b];
        int g = N_USERS + neg[b];
        int c = lane * 2;
        float2 eu = *(const float2*)(emb + (size_t)n * EMB + c);
        float2 ep = *(const float2*)(emb + (size_t)p * EMB + c);
        float2 eg = *(const float2*)(emb + (size_t)g * EMB + c);
        float sum = eu.x * eu.x + eu.y * eu.y
                  + ep.x * ep.x + ep.y * ep.y
                  + eg.x * eg.x + eg.y * eg.y;
        #pragma unroll
        for (int off = 16; off > 0; off >>= 1)
            sum += __shfl_xor_sync(0xFFFFFFFFu, sum, off);
        if (lane == 0)
            out[(size_t)3 * BATCH * EMB + b] = sum;
    }
}

// ---------------------------------------------------------------------------
extern "C" void kernel_launch(void* const* d_in, const int* in_sizes, int n_in,
                              void* d_out, int out_size) {
    const float* emb   = (const float*)d_in[0];
    const int*   eu    = (const int*)  d_in[1];
    const int*   ei    = (const int*)  d_in[2];
    const int*   users = (const int*)  d_in[3];
    const int*   pos   = (const int*)  d_in[4];
    const int*   neg   = (const int*)  d_in[5];
    float* out = (float*)d_out;
    const int E = in_sizes[1];

    __half *q0, *q1, *q2;
    float *dinv;
    int *deg, *rs, *col, *bsum;
    ushort2 *slots;
    cudaGetSymbolAddress((void**)&q0,    g_q0);
    cudaGetSymbolAddress((void**)&q1,    g_q1);
    cudaGetSymbolAddress((void**)&q2,    g_q2);
    cudaGetSymbolAddress((void**)&dinv,  g_dinv);
    cudaGetSymbolAddress((void**)&deg,   g_deg);
    cudaGetSymbolAddress((void**)&rs,    g_rs);
    cudaGetSymbolAddress((void**)&slots, g_slots);
    cudaGetSymbolAddress((void**)&col,   g_col);
    cudaGetSymbolAddress((void**)&bsum,  g_bsum);

    const int TB = 256;

    // ---- CSR build (deg zeroed at load / by previous replay's k_scanB) ----
    k_hist<<<(E + TB - 1) / TB, TB>>>(eu, ei, deg, slots, E);
    k_scan1<<<SCAN_BLOCKS, SCAN_T>>>(deg, rs, bsum, dinv, (const float4*)emb,
                                     (uint2*)q0);
    k_scanB<<<SCAN_BLOCKS, SCAN_T>>>(rs, bsum, deg, col);
    k_fill<<<(E + TB - 1) / TB, TB>>>(eu, ei, slots, rs, col, E);

    // ---- layers 1 & 2 ----
    const int pullBlocks = (N_NODES * 32 + TB - 1) / TB;
    k_pull_h<<<pullBlocks, TB>>>(q0, q1, rs, col, dinv);
    k_pull_h<<<pullBlocks, TB>>>(q1, q2, rs, col, dinv);

    // ---- fused layer 3 + epilogue ----
    const int finalBlocks = (3 * BATCH * 32 + TB - 1) / TB;
    k_final<<<finalBlocks, TB>>>(out, emb, q1, q2, rs, col, dinv,
                                 users, pos, neg);
}

// round 13
// speedup vs baseline: 1.6236x; 1.1716x over previous
#include <cuda_runtime.h>
#include <cuda_fp16.h>
#include <cstdint>

#define N_USERS 100000
#define N_ITEMS 50000
#define N_NODES (N_USERS + N_ITEMS)
#define EMB 64
#define BATCH 4096
#define E_MAX 1500000
#define QROWS (N_NODES + 1)            // last row = permanent zero (dummy pad target)

// ---- static scratch (no allocations; zero-initialized at module load) ----
__device__ __half  g_q0[(size_t)QROWS * EMB];    // dinv*emb  (row N_NODES stays 0)
__device__ __half  g_q1[(size_t)QROWS * EMB];
__device__ __half  g_q2[(size_t)QROWS * EMB];
__device__ float   g_dinv [N_NODES];
__device__ int     g_deg  [N_NODES];             // real degree; zeroed by k_scanB each replay
__device__ int     g_rs   [N_NODES + 1];         // padded-degree exclusive scan
__device__ ushort2 g_slots[E_MAX];               // per-interaction row-local slots (6 MB)
__device__ int     g_col  [2 * E_MAX + 4 * N_NODES + 16];  // ~13.8 MB compact+pad
__device__ int     g_bsum [256];

#define SCAN_T 1024
#define SCAN_BLOCKS ((N_NODES + SCAN_T - 1) / SCAN_T)   // 147

// ---------------------------------------------------------------------------
// Degree histogram; the atomic return value IS the edge's row-local slot.
__global__ void k_hist(const int* __restrict__ eu, const int* __restrict__ ei,
                       int* __restrict__ deg, ushort2* __restrict__ slots, int E) {
    int i = blockIdx.x * blockDim.x + threadIdx.x;
    if (i >= E) return;
    int s1 = atomicAdd(&deg[eu[i]], 1);
    int s2 = atomicAdd(&deg[ei[i] + N_USERS], 1);
    slots[i] = make_ushort2((unsigned short)s1, (unsigned short)s2);
}

// Block-local exclusive scan of PADDED degree -> rs (pre-offset), bsum,
// dinv = rsqrt(real deg), and COALESCED q0 = dinv*emb conversion.
__global__ void k_scan1(const int* __restrict__ deg, int* __restrict__ rs,
                        int* __restrict__ bsum, float* __restrict__ dinv,
                        const float4* __restrict__ emb, uint2* __restrict__ q0) {
    __shared__ int sh[SCAN_T];
    __shared__ float shd[SCAN_T];
    int gid = blockIdx.x * SCAN_T + threadIdx.x;
    int real = (gid < N_NODES) ? deg[gid] : 0;
    int v = (real + 3) & ~3;                        // padded degree
    float d = (real > 0) ? rsqrtf((float)real) : 1.0f;
    if (gid < N_NODES) dinv[gid] = d;
    shd[threadIdx.x] = d;
    sh[threadIdx.x] = v;
    __syncthreads();
    for (int off = 1; off < SCAN_T; off <<= 1) {
        int t = (threadIdx.x >= off) ? sh[threadIdx.x - off] : 0;
        __syncthreads();
        sh[threadIdx.x] += t;
        __syncthreads();
    }
    if (gid < N_NODES) rs[gid] = sh[threadIdx.x] - v;   // exclusive (pre-offset)
    if (threadIdx.x == SCAN_T - 1) bsum[blockIdx.x] = sh[threadIdx.x];

    // coalesced q0 conversion for this block's node range
    int baseNode = blockIdx.x * SCAN_T;
    int nodesHere = N_NODES - baseNode;
    if (nodesHere > SCAN_T) nodesHere = SCAN_T;
    int elems = nodesHere * (EMB / 4);              // float4 / uint2 elements
    for (int j = threadIdx.x; j < elems; j += SCAN_T) {
        int node = j >> 4;                          // EMB/4 == 16
        float dd = shd[node];
        float4 x = emb[(size_t)(baseNode + node) * (EMB / 4) + (j & 15)];
        __half2 a = __floats2half2_rn(x.x * dd, x.y * dd);
        __half2 b = __floats2half2_rn(x.z * dd, x.w * dd);
        uint2 o;
        o.x = *(unsigned*)&a;
        o.y = *(unsigned*)&b;
        q0[(size_t)(baseNode + node) * (EMB / 4) + (j & 15)] = o;
    }
}

// Merged scan2+scan3+pad: scans the 147 block sums redundantly, offsets rs,
// pre-writes the <=3 pad slots per row, zeroes deg for next replay, sentinel.
__global__ void k_scanB(int* __restrict__ rs, const int* __restrict__ bsum,
                        int* __restrict__ deg, int* __restrict__ col) {
    __shared__ int sh[256];
    int t = threadIdx.x;
    int v = 0;
    if (t < 256) {
        v = (t < SCAN_BLOCKS) ? bsum[t] : 0;
        sh[t] = v;
    }
    __syncthreads();
    for (int off = 1; off < 256; off <<= 1) {
        int tmp = (t < 256 && t >= off) ? sh[t - off] : 0;
        __syncthreads();
        if (t < 256) sh[t] += tmp;
        __syncthreads();
    }
    if (t < 256) sh[t] -= v;   // exclusive
    __syncthreads();

    int gid = blockIdx.x * SCAN_T + t;
    if (gid < N_NODES) {
        int r = rs[gid] + sh[blockIdx.x];
        rs[gid] = r;
        int real = deg[gid];
        deg[gid] = 0;                               // ready for next graph replay
        int pads = ((real + 3) & ~3) - real;        // 0..3
        int base = r + real;
        for (int k = 0; k < pads; ++k) col[base + k] = N_NODES;
    }
    if (blockIdx.x == 0 && t == 0)
        rs[N_NODES] = sh[SCAN_BLOCKS - 1] + bsum[SCAN_BLOCKS - 1];
}

// Atomic-free CSR fill: slot precomputed in k_hist, offset via rs gather.
__global__ void k_fill(const int* __restrict__ eu, const int* __restrict__ ei,
                       const ushort2* __restrict__ slots,
                       const int* __restrict__ rs, int* __restrict__ col, int E) {
    int i = blockIdx.x * blockDim.x + threadIdx.x;
    if (i >= E) return;
    int u  = eu[i];
    int it = ei[i] + N_USERS;
    ushort2 s = slots[i];
    col[__ldg(rs + u)  + s.x] = it;
    col[__ldg(rs + it) + s.y] = u;
}

// ---------------------------------------------------------------------------
// Quarter-warp row gather-sum: 8 lanes own one node; lane `sub` owns columns
// [sub*8, sub*8+8). Per iteration the quarter processes 4 edges (broadcast
// int4 col load + 4 LDG.128). fp16 tree accumulation.
// NO cross-lane reduction needed: each lane's hacc is its final column sum.
__device__ __forceinline__ void row_sum_q(const __half* __restrict__ qin,
                                          const int* __restrict__ col,
                                          int beg, int end, int sub,
                                          __half2 hacc[4]) {
    __half2 hz = __floats2half2_rn(0.0f, 0.0f);
    hacc[0] = hz; hacc[1] = hz; hacc[2] = hz; hacc[3] = hz;

    const uint4* q4 = (const uint4*)qin;

    for (int e0 = beg; e0 < end; e0 += 4) {
        int4 c4 = *(const int4*)(col + e0);     // 16B-aligned (beg % 4 == 0)
        uint4 va = q4[(unsigned)c4.x * (EMB / 8) + sub];
        uint4 vb = q4[(unsigned)c4.y * (EMB / 8) + sub];
        uint4 vc = q4[(unsigned)c4.z * (EMB / 8) + sub];
        uint4 vd = q4[(unsigned)c4.w * (EMB / 8) + sub];
        const __half2* ha = (const __half2*)&va;
        const __half2* hb = (const __half2*)&vb;
        const __half2* hc = (const __half2*)&vc;
        const __half2* hd = (const __half2*)&vd;
        #pragma unroll
        for (int k = 0; k < 4; ++k) {
            __half2 t0 = __hadd2(ha[k], hb[k]);
            __half2 t1 = __hadd2(hc[k], hd[k]);
            hacc[k] = __hadd2(hacc[k], __hadd2(t0, t1));
        }
    }
}

// Pull layer: qout[n] = dinv[n]^2 * sum_{s in N(n)} qin[s].
// Quarter-warp per node; warp covers 4 consecutive nodes (coalesced 512B store).
__global__ void __launch_bounds__(256)
k_pull_h(const __half* __restrict__ qin, __half* __restrict__ qout,
         const int* __restrict__ rs, const int* __restrict__ col,
         const float* __restrict__ dinv) {
    int tid = blockIdx.x * blockDim.x + threadIdx.x;
    int n = tid >> 3;
    if (n >= N_NODES) return;
    int sub = tid & 7;

    __half2 hacc[4];
    row_sum_q(qin, col, __ldg(rs + n), __ldg(rs + n + 1), sub, hacc);

    float d = dinv[n];
    float s = d * d;
    uint4 o;
    {
        float2 f0 = __half22float2(hacc[0]);
        float2 f1 = __half22float2(hacc[1]);
        float2 f2 = __half22float2(hacc[2]);
        float2 f3 = __half22float2(hacc[3]);
        __half2 h0 = __floats2half2_rn(f0.x * s, f0.y * s);
        __half2 h1 = __floats2half2_rn(f1.x * s, f1.y * s);
        __half2 h2 = __floats2half2_rn(f2.x * s, f2.y * s);
        __half2 h3 = __floats2half2_rn(f3.x * s, f3.y * s);
        o.x = *(unsigned*)&h0; o.y = *(unsigned*)&h1;
        o.z = *(unsigned*)&h2; o.w = *(unsigned*)&h3;
    }
    *((uint4*)(qout + (size_t)n * EMB) + sub) = o;
}

// ---------------------------------------------------------------------------
// Fused layer-3 + epilogue, quarter-warp per (role, batch-row):
//   rep3 = dinv[n] * sum q2[s]
//   final = 0.25 * ( emb[n] + sq*(q1[n]+q2[n]) + rep3 ),  sq = 1/dinv[n]
// role-0 quarters also compute l2_norm_sq (intra-quarter shfl reduce).
__global__ void __launch_bounds__(256)
k_final(float* __restrict__ out,
        const float* __restrict__ emb,
        const __half* __restrict__ q1,
        const __half* __restrict__ q2,
        const int* __restrict__ rs, const int* __restrict__ col,
        const float* __restrict__ dinv,
        const int* __restrict__ users, const int* __restrict__ pos,
        const int* __restrict__ neg) {
    int tid = blockIdx.x * blockDim.x + threadIdx.x;
    int w = tid >> 3;                      // quarter index = (role, b)
    if (w >= 3 * BATCH) return;
    int sub = tid & 7;

    int role = w / BATCH;
    int b = w - role * BATCH;
    int n = (role == 0) ? users[b]
          : (role == 1) ? (N_USERS + pos[b])
                        : (N_USERS + neg[b]);

    __half2 hacc[4];
    row_sum_q(q2, col, __ldg(rs + n), __ldg(rs + n + 1), sub, hacc);

    float d = dinv[n];
    float sq = __fdividef(1.0f, d);        // sqrt(deg), or 1 when deg==0
    size_t ro = (size_t)n * EMB + sub * 8;

    float4 e0 = *(const float4*)(emb + ro);
    float4 e1 = *(const float4*)(emb + ro + 4);
    uint4 a1 = *((const uint4*)(q1 + (size_t)n * EMB) + sub);
    uint4 a2 = *((const uint4*)(q2 + (size_t)n * EMB) + sub);
    const __half2* h1 = (const __half2*)&a1;
    const __half2* h2 = (const __half2*)&a2;

    float r[8];
    #pragma unroll
    for (int k = 0; k < 4; ++k) {
        float2 f1 = __half22float2(h1[k]);
        float2 f2 = __half22float2(h2[k]);
        float2 fa = __half22float2(hacc[k]);
        r[2*k]   = sq * (f1.x + f2.x) + d * fa.x;
        r[2*k+1] = sq * (f1.y + f2.y) + d * fa.y;
    }
    float4 o0, o1;
    o0.x = (e0.x + r[0]) * 0.25f; o0.y = (e0.y + r[1]) * 0.25f;
    o0.z = (e0.z + r[2]) * 0.25f; o0.w = (e0.w + r[3]) * 0.25f;
    o1.x = (e1.x + r[4]) * 0.25f; o1.y = (e1.y + r[5]) * 0.25f;
    o1.z = (e1.z + r[6]) * 0.25f; o1.w = (e1.w + r[7]) * 0.25f;

    size_t wo = (size_t)(role * BATCH + b) * EMB + sub * 8;
    *(float4*)(out + wo)     = o0;
    *(float4*)(out + wo + 4) = o1;

    if (role == 0) {
        int p = N_USERS + pos[b];
        int g = N_USERS + neg[b];
        size_t po = (size_t)p * EMB + sub * 8;
        size_t go = (size_t)g * EMB + sub * 8;
        float4 p0 = *(const float4*)(emb + po);
        float4 p1 = *(const float4*)(emb + po + 4);
        float4 g0 = *(const float4*)(emb + go);
        float4 g1 = *(const float4*)(emb + go + 4);
        float sum = e0.x*e0.x + e0.y*e0.y + e0.z*e0.z + e0.w*e0.w
                  + e1.x*e1.x + e1.y*e1.y + e1.z*e1.z + e1.w*e1.w
                  + p0.x*p0.x + p0.y*p0.y + p0.z*p0.z + p0.w*p0.w
                  + p1.x*p1.x + p1.y*p1.y + p1.z*p1.z + p1.w*p1.w
                  + g0.x*g0.x + g0.y*g0.y + g0.z*g0.z + g0.w*g0.w
                  + g1.x*g1.x + g1.y*g1.y + g1.z*g1.z + g1.w*g1.w;
        sum += __shfl_xor_sync(0xFFFFFFFFu, sum, 1);
        sum += __shfl_xor_sync(0xFFFFFFFFu, sum, 2);
        sum += __shfl_xor_sync(0xFFFFFFFFu, sum, 4);
        if (sub == 0)
            out[(size_t)3 * BATCH * EMB + b] = sum;
    }
}

// ---------------------------------------------------------------------------
extern "C" void kernel_launch(void* const* d_in, const int* in_sizes, int n_in,
                              void* d_out, int out_size) {
    const float* emb   = (const float*)d_in[0];
    const int*   eu    = (const int*)  d_in[1];
    const int*   ei    = (const int*)  d_in[2];
    const int*   users = (const int*)  d_in[3];
    const int*   pos   = (const int*)  d_in[4];
    const int*   neg   = (const int*)  d_in[5];
    float* out = (float*)d_out;
    const int E = in_sizes[1];

    __half *q0, *q1, *q2;
    float *dinv;
    int *deg, *rs, *col, *bsum;
    ushort2 *slots;
    cudaGetSymbolAddress((void**)&q0,    g_q0);
    cudaGetSymbolAddress((void**)&q1,    g_q1);
    cudaGetSymbolAddress((void**)&q2,    g_q2);
    cudaGetSymbolAddress((void**)&dinv,  g_dinv);
    cudaGetSymbolAddress((void**)&deg,   g_deg);
    cudaGetSymbolAddress((void**)&rs,    g_rs);
    cudaGetSymbolAddress((void**)&slots, g_slots);
    cudaGetSymbolAddress((void**)&col,   g_col);
    cudaGetSymbolAddress((void**)&bsum,  g_bsum);

    const int TB = 256;

    // ---- CSR build (deg zeroed at load / by previous replay's k_scanB) ----
    k_hist<<<(E + TB - 1) / TB, TB>>>(eu, ei, deg, slots, E);
    k_scan1<<<SCAN_BLOCKS, SCAN_T>>>(deg, rs, bsum, dinv, (const float4*)emb,
                                     (uint2*)q0);
    k_scanB<<<SCAN_BLOCKS, SCAN_T>>>(rs, bsum, deg, col);
    k_fill<<<(E + TB - 1) / TB, TB>>>(eu, ei, slots, rs, col, E);

    // ---- layers 1 & 2 (quarter-warp per node) ----
    const int pullBlocks = (N_NODES * 8 + TB - 1) / TB;
    k_pull_h<<<pullBlocks, TB>>>(q0, q1, rs, col, dinv);
    k_pull_h<<<pullBlocks, TB>>>(q1, q2, rs, col, dinv);

    // ---- fused layer 3 + epilogue ----
    const int finalBlocks = (3 * BATCH * 8 + TB - 1) / TB;
    k_final<<<finalBlocks, TB>>>(out, emb, q1, q2, rs, col, dinv,
                                 users, pos, neg);
}

// round 16
// speedup vs baseline: 1.6267x; 1.0019x over previous
#include <cuda_runtime.h>
#include <cuda_fp16.h>
#include <cstdint>

#define N_USERS 100000
#define N_ITEMS 50000
#define N_NODES (N_USERS + N_ITEMS)
#define EMB 64
#define BATCH 4096
#define E_MAX 1500000
#define QROWS (N_NODES + 1)            // last row = permanent zero (dummy pad target)

// ---- static scratch (no allocations; zero-initialized at module load) ----
__device__ __half  g_q0[(size_t)QROWS * EMB];    // dinv*emb  (row N_NODES stays 0)
__device__ __half  g_q1[(size_t)QROWS * EMB];
__device__ __half  g_q2[(size_t)QROWS * EMB];
__device__ float   g_dinv [N_NODES];
__device__ int     g_deg  [N_NODES];             // real degree; zeroed by k_scanA each replay
__device__ int     g_rs   [N_NODES];             // row start (block-local scan + atomic base)
__device__ int     g_dgp  [N_NODES];             // padded degree (row extent)
__device__ ushort2 g_slots[E_MAX];               // per-interaction row-local slots
__device__ int     g_col  [2 * E_MAX + 4 * N_NODES + 16];  // ~13.8 MB compact+pad
__device__ unsigned g_alloc = 0;                 // col-space allocation cursor

#define SCAN_T 1024
#define SCAN_BLOCKS ((N_NODES + SCAN_T - 1) / SCAN_T)   // 147

// ---------------------------------------------------------------------------
// Degree histogram; the atomic return value IS the edge's row-local slot.
// Thread 0 also resets the col-space allocator for this replay (k_scanA,
// which consumes it, is ordered after this kernel by the stream).
__global__ void k_hist(const int* __restrict__ eu, const int* __restrict__ ei,
                       int* __restrict__ deg, ushort2* __restrict__ slots,
                       unsigned* __restrict__ alloc, int E) {
    int i = blockIdx.x * blockDim.x + threadIdx.x;
    if (i == 0) *alloc = 0u;
    if (i >= E) return;
    int s1 = atomicAdd(&deg[eu[i]], 1);
    int s2 = atomicAdd(&deg[ei[i] + N_USERS], 1);
    slots[i] = make_ushort2((unsigned short)s1, (unsigned short)s2);
}

// Single-launch CSR layout: block-local scan of padded degrees, col-space base
// via one atomicAdd per block (row placement need not be globally ordered —
// any disjoint partition works). Writes rs, dgp, dinv, pad slots, q0, and
// zeroes deg for the next replay.
__global__ void k_scanA(int* __restrict__ deg, int* __restrict__ rs,
                        int* __restrict__ dgp, float* __restrict__ dinv,
                        int* __restrict__ col, unsigned* __restrict__ alloc,
                        const float4* __restrict__ emb, uint2* __restrict__ q0) {
    __shared__ int   sh[SCAN_T];
    __shared__ float shd[SCAN_T];
    __shared__ int   shbase;

    int gid = blockIdx.x * SCAN_T + threadIdx.x;
    int real = 0;
    if (gid < N_NODES) {
        real = deg[gid];
        deg[gid] = 0;                               // ready for next graph replay
    }
    int v = (real + 3) & ~3;                        // padded degree
    float d = (real > 0) ? rsqrtf((float)real) : 1.0f;
    if (gid < N_NODES) dinv[gid] = d;
    shd[threadIdx.x] = d;
    sh[threadIdx.x] = v;
    __syncthreads();
    for (int off = 1; off < SCAN_T; off <<= 1) {
        int t = (threadIdx.x >= off) ? sh[threadIdx.x - off] : 0;
        __syncthreads();
        sh[threadIdx.x] += t;
        __syncthreads();
    }
    if (threadIdx.x == SCAN_T - 1)
        shbase = (int)atomicAdd(alloc, (unsigned)sh[SCAN_T - 1]);
    __syncthreads();

    if (gid < N_NODES) {
        int r = shbase + sh[threadIdx.x] - v;       // exclusive local + block base
        rs[gid] = r;
        dgp[gid] = v;
        for (int k = real; k < v; ++k) col[r + k] = N_NODES;   // pad slots
    }

    // coalesced q0 conversion for this block's node range
    int baseNode = blockIdx.x * SCAN_T;
    int nodesHere = N_NODES - baseNode;
    if (nodesHere > SCAN_T) nodesHere = SCAN_T;
    int elems = nodesHere * (EMB / 4);              // float4 / uint2 elements
    for (int j = threadIdx.x; j < elems; j += SCAN_T) {
        int node = j >> 4;                          // EMB/4 == 16
        float dd = shd[node];
        float4 x = emb[(size_t)(baseNode + node) * (EMB / 4) + (j & 15)];
        __half2 a = __floats2half2_rn(x.x * dd, x.y * dd);
        __half2 b = __floats2half2_rn(x.z * dd, x.w * dd);
        uint2 o;
        o.x = *(unsigned*)&a;
        o.y = *(unsigned*)&b;
        q0[(size_t)(baseNode + node) * (EMB / 4) + (j & 15)] = o;
    }
}

// Atomic-free CSR fill: slot precomputed in k_hist, offset via rs gather.
__global__ void k_fill(const int* __restrict__ eu, const int* __restrict__ ei,
                       const ushort2* __restrict__ slots,
                       const int* __restrict__ rs, int* __restrict__ col, int E) {
    int i = blockIdx.x * blockDim.x + threadIdx.x;
    if (i >= E) return;
    int u  = eu[i];
    int it = ei[i] + N_USERS;
    ushort2 s = slots[i];
    col[__ldg(rs + u)  + s.x] = it;
    col[__ldg(rs + it) + s.y] = u;
}

// ---------------------------------------------------------------------------
// Quarter-warp row gather-sum: 8 lanes own one node; lane `sub` owns columns
// [sub*8, sub*8+8). fp16 tree accumulation; no cross-lane reduction needed.
__device__ __forceinline__ void row_sum_q(const __half* __restrict__ qin,
                                          const int* __restrict__ col,
                                          int beg, int end, int sub,
                                          __half2 hacc[4]) {
    __half2 hz = __floats2half2_rn(0.0f, 0.0f);
    hacc[0] = hz; hacc[1] = hz; hacc[2] = hz; hacc[3] = hz;

    const uint4* q4 = (const uint4*)qin;

    for (int e0 = beg; e0 < end; e0 += 4) {
        int4 c4 = *(const int4*)(col + e0);     // 16B-aligned (beg % 4 == 0)
        uint4 va = q4[(unsigned)c4.x * (EMB / 8) + sub];
        uint4 vb = q4[(unsigned)c4.y * (EMB / 8) + sub];
        uint4 vc = q4[(unsigned)c4.z * (EMB / 8) + sub];
        uint4 vd = q4[(unsigned)c4.w * (EMB / 8) + sub];
        const __half2* ha = (const __half2*)&va;
        const __half2* hb = (const __half2*)&vb;
        const __half2* hc = (const __half2*)&vc;
        const __half2* hd = (const __half2*)&vd;
        #pragma unroll
        for (int k = 0; k < 4; ++k) {
            __half2 t0 = __hadd2(ha[k], hb[k]);
            __half2 t1 = __hadd2(hc[k], hd[k]);
            hacc[k] = __hadd2(hacc[k], __hadd2(t0, t1));
        }
    }
}

// Pull layer: qout[n] = dinv[n]^2 * sum_{s in N(n)} qin[s].
__global__ void __launch_bounds__(256)
k_pull_h(const __half* __restrict__ qin, __half* __restrict__ qout,
         const int* __restrict__ rs, const int* __restrict__ dgp,
         const int* __restrict__ col, const float* __restrict__ dinv) {
    int tid = blockIdx.x * blockDim.x + threadIdx.x;
    int n = tid >> 3;
    if (n >= N_NODES) return;
    int sub = tid & 7;

    int beg = __ldg(rs + n);
    int end = beg + __ldg(dgp + n);

    __half2 hacc[4];
    row_sum_q(qin, col, beg, end, sub, hacc);

    float d = dinv[n];
    float s = d * d;
    uint4 o;
    {
        float2 f0 = __half22float2(hacc[0]);
        float2 f1 = __half22float2(hacc[1]);
        float2 f2 = __half22float2(hacc[2]);
        float2 f3 = __half22float2(hacc[3]);
        __half2 h0 = __floats2half2_rn(f0.x * s, f0.y * s);
        __half2 h1 = __floats2half2_rn(f1.x * s, f1.y * s);
        __half2 h2 = __floats2half2_rn(f2.x * s, f2.y * s);
        __half2 h3 = __floats2half2_rn(f3.x * s, f3.y * s);
        o.x = *(unsigned*)&h0; o.y = *(unsigned*)&h1;
        o.z = *(unsigned*)&h2; o.w = *(unsigned*)&h3;
    }
    *((uint4*)(qout + (size_t)n * EMB) + sub) = o;
}

// ---------------------------------------------------------------------------
// Fused layer-3 + epilogue, quarter-warp per (role, batch-row).
__global__ void __launch_bounds__(256)
k_final(float* __restrict__ out,
        const float* __restrict__ emb,
        const __half* __restrict__ q1,
        const __half* __restrict__ q2,
        const int* __restrict__ rs, const int* __restrict__ dgp,
        const int* __restrict__ col, const float* __restrict__ dinv,
        const int* __restrict__ users, const int* __restrict__ pos,
        const int* __restrict__ neg) {
    int tid = blockIdx.x * blockDim.x + threadIdx.x;
    int w = tid >> 3;                      // quarter index = (role, b)
    if (w >= 3 * BATCH) return;
    int sub = tid & 7;

    int role = w / BATCH;
    int b = w - role * BATCH;
    int n = (role == 0) ? users[b]
          : (role == 1) ? (N_USERS + pos[b])
                        : (N_USERS + neg[b]);

    int beg = __ldg(rs + n);
    int end = beg + __ldg(dgp + n);

    __half2 hacc[4];
    row_sum_q(q2, col, beg, end, sub, hacc);

    float d = dinv[n];
    float sq = __fdividef(1.0f, d);        // sqrt(deg), or 1 when deg==0
    size_t ro = (size_t)n * EMB + sub * 8;

    float4 e0 = *(const float4*)(emb + ro);
    float4 e1 = *(const float4*)(emb + ro + 4);
    uint4 a1 = *((const uint4*)(q1 + (size_t)n * EMB) + sub);
    uint4 a2 = *((const uint4*)(q2 + (size_t)n * EMB) + sub);
    const __half2* h1 = (const __half2*)&a1;
    const __half2* h2 = (const __half2*)&a2;

    float r[8];
    #pragma unroll
    for (int k = 0; k < 4; ++k) {
        float2 f1 = __half22float2(h1[k]);
        float2 f2 = __half22float2(h2[k]);
        float2 fa = __half22float2(hacc[k]);
        r[2*k]   = sq * (f1.x + f2.x) + d * fa.x;
        r[2*k+1] = sq * (f1.y + f2.y) + d * fa.y;
    }
    float4 o0, o1;
    o0.x = (e0.x + r[0]) * 0.25f; o0.y = (e0.y + r[1]) * 0.25f;
    o0.z = (e0.z + r[2]) * 0.25f; o0.w = (e0.w + r[3]) * 0.25f;
    o1.x = (e1.x + r[4]) * 0.25f; o1.y = (e1.y + r[5]) * 0.25f;
    o1.z = (e1.z + r[6]) * 0.25f; o1.w = (e1.w + r[7]) * 0.25f;

    size_t wo = (size_t)(role * BATCH + b) * EMB + sub * 8;
    *(float4*)(out + wo)     = o0;
    *(float4*)(out + wo + 4) = o1;

    if (role == 0) {
        int p = N_USERS + pos[b];
        int g = N_USERS + neg[b];
        size_t po = (size_t)p * EMB + sub * 8;
        size_t go = (size_t)g * EMB + sub * 8;
        float4 p0 = *(const float4*)(emb + po);
        float4 p1 = *(const float4*)(emb + po + 4);
        float4 g0 = *(const float4*)(emb + go);
        float4 g1 = *(const float4*)(emb + go + 4);
        float sum = e0.x*e0.x + e0.y*e0.y + e0.z*e0.z + e0.w*e0.w
                  + e1.x*e1.x + e1.y*e1.y + e1.z*e1.z + e1.w*e1.w
                  + p0.x*p0.x + p0.y*p0.y + p0.z*p0.z + p0.w*p0.w
                  + p1.x*p1.x + p1.y*p1.y + p1.z*p1.z + p1.w*p1.w
                  + g0.x*g0.x + g0.y*g0.y + g0.z*g0.z + g0.w*g0.w
                  + g1.x*g1.x + g1.y*g1.y + g1.z*g1.z + g1.w*g1.w;
        sum += __shfl_xor_sync(0xFFFFFFFFu, sum, 1);
        sum += __shfl_xor_sync(0xFFFFFFFFu, sum, 2);
        sum += __shfl_xor_sync(0xFFFFFFFFu, sum, 4);
        if (sub == 0)
            out[(size_t)3 * BATCH * EMB + b] = sum;
    }
}

// ---------------------------------------------------------------------------
extern "C" void kernel_launch(void* const* d_in, const int* in_sizes, int n_in,
                              void* d_out, int out_size) {
    const float* emb   = (const float*)d_in[0];
    const int*   eu    = (const int*)  d_in[1];
    const int*   ei    = (const int*)  d_in[2];
    const int*   users = (const int*)  d_in[3];
    const int*   pos   = (const int*)  d_in[4];
    const int*   neg   = (const int*)  d_in[5];
    float* out = (float*)d_out;
    const int E = in_sizes[1];

    __half *q0, *q1, *q2;
    float *dinv;
    int *deg, *rs, *dgp, *col;
    ushort2 *slots;
    unsigned *alloc;
    cudaGetSymbolAddress((void**)&q0,    g_q0);
    cudaGetSymbolAddress((void**)&q1,    g_q1);
    cudaGetSymbolAddress((void**)&q2,    g_q2);
    cudaGetSymbolAddress((void**)&dinv,  g_dinv);
    cudaGetSymbolAddress((void**)&deg,   g_deg);
    cudaGetSymbolAddress((void**)&rs,    g_rs);
    cudaGetSymbolAddress((void**)&dgp,   g_dgp);
    cudaGetSymbolAddress((void**)&slots, g_slots);
    cudaGetSymbolAddress((void**)&col,   g_col);
    cudaGetSymbolAddress((void**)&alloc, g_alloc);

    const int TB = 256;

    // ---- CSR build: 3 launches (deg zeroed at load / by prior k_scanA) ----
    k_hist<<<(E + TB - 1) / TB, TB>>>(eu, ei, deg, slots, alloc, E);
    k_scanA<<<SCAN_BLOCKS, SCAN_T>>>(deg, rs, dgp, dinv, col, alloc,
                                     (const float4*)emb, (uint2*)q0);
    k_fill<<<(E + TB - 1) / TB, TB>>>(eu, ei, slots, rs, col, E);

    // ---- layers 1 & 2 (quarter-warp per node) ----
    const int pullBlocks = (N_NODES * 8 + TB - 1) / TB;
    k_pull_h<<<pullBlocks, TB>>>(q0, q1, rs, dgp, col, dinv);
    k_pull_h<<<pullBlocks, TB>>>(q1, q2, rs, dgp, col, dinv);

    // ---- fused layer 3 + epilogue ----
    const int finalBlocks = (3 * BATCH * 8 + TB - 1) / TB;
    k_final<<<finalBlocks, TB>>>(out, emb, q1, q2, rs, dgp, col, dinv,
                                 users, pos, neg);
}